// round 13
// baseline (speedup 1.0000x reference)
#include <cuda_runtime.h>
#include <cuda_bf16.h>
#include <cstdint>

#define C_DIM 272
#define T_DIM 1024
#define BATCH 128
#define MT 64
#define NT 256
#define PIT 12                 // u32 per smem row (48B): conflict-free ldmatrix
#define AH_OFF 0
#define AL_OFF 768             // 64*PIT
#define BH_OFF 1536
#define BL_OFF 4608            // BH_OFF + 256*PIT
#define BUF_U32 7680
#define SMEM_BYTES (2 * BUF_U32 * 4)

__device__ int g_sidx[BATCH];

__global__ void decode_sidx_kernel(const int* __restrict__ raw) {
    __shared__ int is_i32;
    if (threadIdx.x == 0) is_i32 = 0;
    __syncthreads();
    int t = threadIdx.x;
    if (t < 64 && raw[2 * t + 1] != 0) atomicExch(&is_i32, 1);
    __syncthreads();
    if (t < BATCH) g_sidx[t] = is_i32 ? raw[t] : raw[2 * t];
}

__device__ __forceinline__ uint32_t pk(float e, float o) {
    __nv_bfloat162 p = __floats2bfloat162_rn(e, o);   // low = e (even k)
    return *reinterpret_cast<uint32_t*>(&p);
}
__device__ __forceinline__ void split2(float v, float& hi, float& lo) {
    const __nv_bfloat16 h = __float2bfloat16_rn(v);
    hi = __bfloat162float(h);
    lo = v - hi;
}
__device__ __forceinline__ void mma16(float* d, const uint32_t* a, uint32_t b0, uint32_t b1) {
    asm volatile("mma.sync.aligned.m16n8k16.row.col.f32.bf16.bf16.f32 "
        "{%0,%1,%2,%3}, {%4,%5,%6,%7}, {%8,%9}, {%0,%1,%2,%3};"
        : "+f"(d[0]), "+f"(d[1]), "+f"(d[2]), "+f"(d[3])
        : "r"(a[0]), "r"(a[1]), "r"(a[2]), "r"(a[3]), "r"(b0), "r"(b1));
}
__device__ __forceinline__ void ldsm4(uint32_t* r, uint32_t addr) {
    asm volatile("ldmatrix.sync.aligned.m8n8.x4.shared.b16 {%0,%1,%2,%3}, [%4];"
        : "=r"(r[0]), "=r"(r[1]), "=r"(r[2]), "=r"(r[3]) : "r"(addr));
}
__device__ __forceinline__ uint32_t smem_u32p(const void* p) {
    uint32_t a;
    asm("{ .reg .u64 t; cvta.to.shared.u64 t, %1; cvt.u32.u64 %0, t; }" : "=r"(a) : "l"(p));
    return a;
}

// CTA: 64(chan) x 256(time); 8 warps (2x4), warp tile 32x64.
// bf16 x3 split, m16n8k16, ldmatrix, double-buffered smem.
// Tile order: LDSM -> STS(next) -> LDG(next+1) -> sync -> mma
// (barrier decoupled from the mma tail).
__global__ __launch_bounds__(256, 2)
void mma_gemm_kernel(const float* __restrict__ x, const float* __restrict__ W,
                     float* __restrict__ out) {
    extern __shared__ uint32_t sm[];
    const uint32_t smaddr = smem_u32p(sm);

    const int b = blockIdx.z, oBase = blockIdx.y * MT, tBase = blockIdx.x * NT;
    const int s = g_sidx[b];
    const float* __restrict__ Wb = W + (size_t)s * C_DIM * C_DIM;
    const float* __restrict__ xb = x + (size_t)b * C_DIM * T_DIM;

    const int tid = threadIdx.x, lane = tid & 31, warp = tid >> 5;
    const int wm = (warp >> 2) * 32, wn = (warp & 3) * 64;
    const int fr = lane >> 2, fc = lane & 3;

    const int aC = tid & 63, aKq = (tid >> 6) * 4, kp = aKq >> 1;
    const bool aV = (oBase + aC) < C_DIM;
    const float* aP = Wb + (size_t)(oBase + aC) * C_DIM + aKq;
    const float* bP = xb + tBase + tid;
    const int aWidx = aC * PIT + kp;
    const int bWidx = tid * PIT;

    uint32_t aOffB[2];
#pragma unroll
    for (int mb = 0; mb < 2; mb++) {
        const int row = wm + mb * 16 + (lane & 7) + ((lane >> 3) & 1) * 8;
        aOffB[mb] = (uint32_t)(row * PIT + (lane >> 4) * 4) * 4;
    }
    uint32_t bOffB[4];
#pragma unroll
    for (int nbp = 0; nbp < 4; nbp++) {
        const int row = wn + nbp * 16 + (lane & 7) + ((lane >> 4) & 1) * 8;
        bOffB[nbp] = (uint32_t)(row * PIT + ((lane >> 3) & 1) * 4) * 4;
    }

    float acc[2][8][4];
#pragma unroll
    for (int mb = 0; mb < 2; mb++)
#pragma unroll
        for (int nb = 0; nb < 8; nb++)
#pragma unroll
            for (int j = 0; j < 4; j++) acc[mb][nb][j] = 0.0f;

    float4 aNxt;
    float bNxt[16];

    // helper lambdas expressed inline: prologue loads tile0, commits, loads tile1
    aNxt = aV ? *(const float4*)(aP) : make_float4(0.f, 0.f, 0.f, 0.f);
#pragma unroll
    for (int j = 0; j < 16; j++) bNxt[j] = bP[(size_t)j * T_DIM];
    {
        uint32_t* buf0 = sm;
        float h0, l0, h1, l1, h2, l2, h3, l3;
        split2(aNxt.x, h0, l0); split2(aNxt.y, h1, l1);
        split2(aNxt.z, h2, l2); split2(aNxt.w, h3, l3);
        *(uint64_t*)&buf0[AH_OFF + aWidx] = (uint64_t)pk(h0, h1) | ((uint64_t)pk(h2, h3) << 32);
        *(uint64_t*)&buf0[AL_OFF + aWidx] = (uint64_t)pk(l0, l1) | ((uint64_t)pk(l2, l3) << 32);
#pragma unroll
        for (int j = 0; j < 4; j++) {
            float e0, f0, e1, f1, e2, f2, e3, f3;
            split2(bNxt[4 * j + 0], e0, f0); split2(bNxt[4 * j + 1], e1, f1);
            split2(bNxt[4 * j + 2], e2, f2); split2(bNxt[4 * j + 3], e3, f3);
            *(uint64_t*)&buf0[BH_OFF + bWidx + 2 * j] = (uint64_t)pk(e0, e1) | ((uint64_t)pk(e2, e3) << 32);
            *(uint64_t*)&buf0[BL_OFF + bWidx + 2 * j] = (uint64_t)pk(f0, f1) | ((uint64_t)pk(f2, f3) << 32);
        }
    }
    // prefetch tile 1 into the (now free) staging registers
    aNxt = aV ? *(const float4*)(aP + 16) : make_float4(0.f, 0.f, 0.f, 0.f);
    {
        const float* bPn = bP + (size_t)16 * T_DIM;
#pragma unroll
        for (int j = 0; j < 16; j++) bNxt[j] = bPn[(size_t)j * T_DIM];
    }
    __syncthreads();

    for (int ck = 0; ck < 17; ck++) {   // 272 = 17*16
        const int cur = ck & 1;
        const uint32_t cb = smaddr + (uint32_t)cur * (BUF_U32 * 4);

        // ---- 1. fragment loads for current tile ----
        uint32_t ah[2][4], al[2][4];
#pragma unroll
        for (int mb = 0; mb < 2; mb++) {
            ldsm4(ah[mb], cb + AH_OFF * 4 + aOffB[mb]);
            ldsm4(al[mb], cb + AL_OFF * 4 + aOffB[mb]);
        }
        uint32_t bh[4][4], bl[4][4];
#pragma unroll
        for (int nbp = 0; nbp < 4; nbp++) {
            ldsm4(bh[nbp], cb + BH_OFF * 4 + bOffB[nbp]);
            ldsm4(bl[nbp], cb + BL_OFF * 4 + bOffB[nbp]);
        }

        // ---- 2. commit next tile (regs staged last iter), refill regs, sync ----
        if (ck < 16) {
            uint32_t* bufN = sm + ((ck + 1) & 1) * BUF_U32;
            float h0, l0, h1, l1, h2, l2, h3, l3;
            split2(aNxt.x, h0, l0); split2(aNxt.y, h1, l1);
            split2(aNxt.z, h2, l2); split2(aNxt.w, h3, l3);
            *(uint64_t*)&bufN[AH_OFF + aWidx] = (uint64_t)pk(h0, h1) | ((uint64_t)pk(h2, h3) << 32);
            *(uint64_t*)&bufN[AL_OFF + aWidx] = (uint64_t)pk(l0, l1) | ((uint64_t)pk(l2, l3) << 32);
#pragma unroll
            for (int j = 0; j < 4; j++) {
                float e0, f0, e1, f1, e2, f2, e3, f3;
                split2(bNxt[4 * j + 0], e0, f0); split2(bNxt[4 * j + 1], e1, f1);
                split2(bNxt[4 * j + 2], e2, f2); split2(bNxt[4 * j + 3], e3, f3);
                *(uint64_t*)&bufN[BH_OFF + bWidx + 2 * j] = (uint64_t)pk(e0, e1) | ((uint64_t)pk(e2, e3) << 32);
                *(uint64_t*)&bufN[BL_OFF + bWidx + 2 * j] = (uint64_t)pk(f0, f1) | ((uint64_t)pk(f2, f3) << 32);
            }
            if (ck < 15) {
                const int kn = (ck + 2) * 16;
                aNxt = aV ? *(const float4*)(aP + kn) : make_float4(0.f, 0.f, 0.f, 0.f);
                const float* bPn = bP + (size_t)kn * T_DIM;
#pragma unroll
                for (int j = 0; j < 16; j++) bNxt[j] = bPn[(size_t)j * T_DIM];
            }
            __syncthreads();
        }

        // ---- 3. mma (no barrier below; flows into next tile's LDSM) ----
#pragma unroll
        for (int nbp = 0; nbp < 4; nbp++)
#pragma unroll
            for (int i = 0; i < 2; i++) {
                const int nb = nbp * 2 + i;
                mma16(acc[0][nb], ah[0], bh[nbp][2 * i], bh[nbp][2 * i + 1]);
                mma16(acc[1][nb], ah[1], bh[nbp][2 * i], bh[nbp][2 * i + 1]);
            }
#pragma unroll
        for (int nbp = 0; nbp < 4; nbp++)
#pragma unroll
            for (int i = 0; i < 2; i++) {
                const int nb = nbp * 2 + i;
                mma16(acc[0][nb], al[0], bh[nbp][2 * i], bh[nbp][2 * i + 1]);
                mma16(acc[1][nb], al[1], bh[nbp][2 * i], bh[nbp][2 * i + 1]);
            }
#pragma unroll
        for (int nbp = 0; nbp < 4; nbp++)
#pragma unroll
            for (int i = 0; i < 2; i++) {
                const int nb = nbp * 2 + i;
                mma16(acc[0][nb], ah[0], bl[nbp][2 * i], bl[nbp][2 * i + 1]);
                mma16(acc[1][nb], ah[1], bl[nbp][2 * i], bl[nbp][2 * i + 1]);
            }
    }

    float* __restrict__ ob = out + (size_t)b * C_DIM * T_DIM;
#pragma unroll
    for (int mb = 0; mb < 2; mb++) {
        const int r0 = oBase + wm + mb * 16 + fr;
        const int r1 = r0 + 8;
#pragma unroll
        for (int nb = 0; nb < 8; nb++) {
            const int cc = tBase + wn + nb * 8 + fc * 2;
            if (r0 < C_DIM)
                *(float2*)&ob[(size_t)r0 * T_DIM + cc] =
                    make_float2(acc[mb][nb][0], acc[mb][nb][1]);
            if (r1 < C_DIM)
                *(float2*)&ob[(size_t)r1 * T_DIM + cc] =
                    make_float2(acc[mb][nb][2], acc[mb][nb][3]);
        }
    }
}

extern "C" void kernel_launch(void* const* d_in, const int* in_sizes, int n_in,
                              void* d_out, int out_size) {
    const float* x = (const float*)d_in[0];
    const int* idx = (const int*)d_in[1];
    const float* W = (const float*)d_in[2];
    float* out = (float*)d_out;

    decode_sidx_kernel<<<1, 128>>>(idx);
    cudaFuncSetAttribute(mma_gemm_kernel,
                         cudaFuncAttributeMaxDynamicSharedMemorySize, SMEM_BYTES);
    dim3 grid(T_DIM / NT, (C_DIM + MT - 1) / MT, BATCH);   // (4, 5, 128)
    mma_gemm_kernel<<<grid, 256, SMEM_BYTES>>>(x, W, out);
}

// round 14
// speedup vs baseline: 2.3967x; 2.3967x over previous
#include <cuda_runtime.h>
#include <cuda_fp16.h>
#include <cstdint>

#define C_DIM 272
#define T_DIM 1024
#define BATCH 128
#define MT 64
#define NT 256
#define PIT 12                 // u32 per smem row (48B): conflict-free ldmatrix
#define AH_OFF 0
#define AL_OFF 768             // 64*PIT
#define BH_OFF 1536
#define BUF_U32 4608           // BH_OFF + 256*PIT
#define SMEM_BYTES (2 * BUF_U32 * 4)

__device__ int g_sidx[BATCH];

__global__ void decode_sidx_kernel(const int* __restrict__ raw) {
    __shared__ int is_i32;
    if (threadIdx.x == 0) is_i32 = 0;
    __syncthreads();
    int t = threadIdx.x;
    if (t < 64 && raw[2 * t + 1] != 0) atomicExch(&is_i32, 1);
    __syncthreads();
    if (t < BATCH) g_sidx[t] = is_i32 ? raw[t] : raw[2 * t];
}

// pack two floats as half2 (low = even k, high = odd k)
__device__ __forceinline__ uint32_t pk(float e, float o) {
    __half2 p = __floats2half2_rn(e, o);
    return *reinterpret_cast<uint32_t*>(&p);
}
__device__ __forceinline__ void split2(float v, float& hi, float& lo) {
    const __half h = __float2half_rn(v);
    hi = __half2float(h);
    lo = v - hi;
}
__device__ __forceinline__ void mma16(float* d, const uint32_t* a, uint32_t b0, uint32_t b1) {
    asm volatile("mma.sync.aligned.m16n8k16.row.col.f32.f16.f16.f32 "
        "{%0,%1,%2,%3}, {%4,%5,%6,%7}, {%8,%9}, {%0,%1,%2,%3};"
        : "+f"(d[0]), "+f"(d[1]), "+f"(d[2]), "+f"(d[3])
        : "r"(a[0]), "r"(a[1]), "r"(a[2]), "r"(a[3]), "r"(b0), "r"(b1));
}
__device__ __forceinline__ void ldsm4(uint32_t* r, uint32_t addr) {
    asm volatile("ldmatrix.sync.aligned.m8n8.x4.shared.b16 {%0,%1,%2,%3}, [%4];"
        : "=r"(r[0]), "=r"(r[1]), "=r"(r[2]), "=r"(r[3]) : "r"(addr));
}
__device__ __forceinline__ uint32_t smem_u32p(const void* p) {
    uint32_t a;
    asm("{ .reg .u64 t; cvta.to.shared.u64 t, %1; cvt.u32.u64 %0, t; }" : "=r"(a) : "l"(p));
    return a;
}

// CTA: 64(chan) x 256(time); 8 warps (2x4), warp tile 32x64.
// fp16 asymmetric x2 split (A = Ah+Al, B = Bh), m16n8k16, ldmatrix,
// double-buffered smem, R12 tile order: LDG -> LDSM+mma -> STS -> sync.
__global__ __launch_bounds__(256, 2)
void mma_gemm_kernel(const float* __restrict__ x, const float* __restrict__ W,
                     float* __restrict__ out) {
    extern __shared__ uint32_t sm[];
    const uint32_t smaddr = smem_u32p(sm);

    const int b = blockIdx.z, oBase = blockIdx.y * MT, tBase = blockIdx.x * NT;
    const int s = g_sidx[b];
    const float* __restrict__ Wb = W + (size_t)s * C_DIM * C_DIM;
    const float* __restrict__ xb = x + (size_t)b * C_DIM * T_DIM;

    const int tid = threadIdx.x, lane = tid & 31, warp = tid >> 5;
    const int wm = (warp >> 2) * 32, wn = (warp & 3) * 64;
    const int fr = lane >> 2, fc = lane & 3;

    const int aC = tid & 63, aKq = (tid >> 6) * 4, kp = aKq >> 1;
    const bool aV = (oBase + aC) < C_DIM;
    const float* aP = Wb + (size_t)(oBase + aC) * C_DIM + aKq;
    const float* bP = xb + tBase + tid;
    const int aWidx = aC * PIT + kp;
    const int bWidx = tid * PIT;

    uint32_t aOffB[2];
#pragma unroll
    for (int mb = 0; mb < 2; mb++) {
        const int row = wm + mb * 16 + (lane & 7) + ((lane >> 3) & 1) * 8;
        aOffB[mb] = (uint32_t)(row * PIT + (lane >> 4) * 4) * 4;
    }
    uint32_t bOffB[4];
#pragma unroll
    for (int nbp = 0; nbp < 4; nbp++) {
        const int row = wn + nbp * 16 + (lane & 7) + ((lane >> 4) & 1) * 8;
        bOffB[nbp] = (uint32_t)(row * PIT + ((lane >> 3) & 1) * 4) * 4;
    }

    float acc[2][8][4];
#pragma unroll
    for (int mb = 0; mb < 2; mb++)
#pragma unroll
        for (int nb = 0; nb < 8; nb++)
#pragma unroll
            for (int j = 0; j < 4; j++) acc[mb][nb][j] = 0.0f;

    // prologue: load tile 0 and commit to buffer 0
    float4 aNxt = aV ? *(const float4*)(aP) : make_float4(0.f, 0.f, 0.f, 0.f);
    float bNxt[16];
#pragma unroll
    for (int j = 0; j < 16; j++) bNxt[j] = bP[(size_t)j * T_DIM];

    {
        uint32_t* bufA = sm;
        float h0, l0, h1, l1, h2, l2, h3, l3;
        split2(aNxt.x, h0, l0); split2(aNxt.y, h1, l1);
        split2(aNxt.z, h2, l2); split2(aNxt.w, h3, l3);
        *(uint64_t*)&bufA[AH_OFF + aWidx] = (uint64_t)pk(h0, h1) | ((uint64_t)pk(h2, h3) << 32);
        *(uint64_t*)&bufA[AL_OFF + aWidx] = (uint64_t)pk(l0, l1) | ((uint64_t)pk(l2, l3) << 32);
#pragma unroll
        for (int j = 0; j < 4; j++) {
            *(uint64_t*)&bufA[BH_OFF + bWidx + 2 * j] =
                (uint64_t)pk(bNxt[4 * j + 0], bNxt[4 * j + 1])
                | ((uint64_t)pk(bNxt[4 * j + 2], bNxt[4 * j + 3]) << 32);
        }
    }
    __syncthreads();

    for (int ck = 0; ck < 17; ck++) {   // 272 = 17*16
        const int cur = ck & 1;
        const uint32_t cb = smaddr + (uint32_t)cur * (BUF_U32 * 4);

        // issue next tile's global loads (hide under mma)
        if (ck < 16) {
            const int kn = (ck + 1) * 16;
            aNxt = aV ? *(const float4*)(aP + kn) : make_float4(0.f, 0.f, 0.f, 0.f);
            const float* bPn = bP + (size_t)kn * T_DIM;
#pragma unroll
            for (int j = 0; j < 16; j++) bNxt[j] = bPn[(size_t)j * T_DIM];
        }

        // ---- A fragments via ldmatrix (hi + lo limbs) ----
        uint32_t ah[2][4], al[2][4];
#pragma unroll
        for (int mb = 0; mb < 2; mb++) {
            ldsm4(ah[mb], cb + AH_OFF * 4 + aOffB[mb]);
            ldsm4(al[mb], cb + AL_OFF * 4 + aOffB[mb]);
        }

        // ---- B fragments (hi only) + mma ----
#pragma unroll
        for (int nbq = 0; nbq < 2; nbq++) {
            uint32_t bh[2][4];
#pragma unroll
            for (int p = 0; p < 2; p++)
                ldsm4(bh[p], cb + BH_OFF * 4 + bOffB[nbq * 2 + p]);
            // pass 1: Ah*B
#pragma unroll
            for (int p = 0; p < 2; p++)
#pragma unroll
                for (int i = 0; i < 2; i++) {
                    const int nb = nbq * 4 + p * 2 + i;
                    mma16(acc[0][nb], ah[0], bh[p][2 * i], bh[p][2 * i + 1]);
                    mma16(acc[1][nb], ah[1], bh[p][2 * i], bh[p][2 * i + 1]);
                }
            // pass 2: Al*B
#pragma unroll
            for (int p = 0; p < 2; p++)
#pragma unroll
                for (int i = 0; i < 2; i++) {
                    const int nb = nbq * 4 + p * 2 + i;
                    mma16(acc[0][nb], al[0], bh[p][2 * i], bh[p][2 * i + 1]);
                    mma16(acc[1][nb], al[1], bh[p][2 * i], bh[p][2 * i + 1]);
                }
        }

        // ---- commit next tile into the other buffer, then sync ----
        if (ck < 16) {
            uint32_t* bufN = sm + (cur ^ 1) * BUF_U32;
            float h0, l0, h1, l1, h2, l2, h3, l3;
            split2(aNxt.x, h0, l0); split2(aNxt.y, h1, l1);
            split2(aNxt.z, h2, l2); split2(aNxt.w, h3, l3);
            *(uint64_t*)&bufN[AH_OFF + aWidx] = (uint64_t)pk(h0, h1) | ((uint64_t)pk(h2, h3) << 32);
            *(uint64_t*)&bufN[AL_OFF + aWidx] = (uint64_t)pk(l0, l1) | ((uint64_t)pk(l2, l3) << 32);
#pragma unroll
            for (int j = 0; j < 4; j++) {
                *(uint64_t*)&bufN[BH_OFF + bWidx + 2 * j] =
                    (uint64_t)pk(bNxt[4 * j + 0], bNxt[4 * j + 1])
                    | ((uint64_t)pk(bNxt[4 * j + 2], bNxt[4 * j + 3]) << 32);
            }
            __syncthreads();
        }
    }

    float* __restrict__ ob = out + (size_t)b * C_DIM * T_DIM;
#pragma unroll
    for (int mb = 0; mb < 2; mb++) {
        const int r0 = oBase + wm + mb * 16 + fr;
        const int r1 = r0 + 8;
#pragma unroll
        for (int nb = 0; nb < 8; nb++) {
            const int cc = tBase + wn + nb * 8 + fc * 2;
            if (r0 < C_DIM)
                *(float2*)&ob[(size_t)r0 * T_DIM + cc] =
                    make_float2(acc[mb][nb][0], acc[mb][nb][1]);
            if (r1 < C_DIM)
                *(float2*)&ob[(size_t)r1 * T_DIM + cc] =
                    make_float2(acc[mb][nb][2], acc[mb][nb][3]);
        }
    }
}

extern "C" void kernel_launch(void* const* d_in, const int* in_sizes, int n_in,
                              void* d_out, int out_size) {
    const float* x = (const float*)d_in[0];
    const int* idx = (const int*)d_in[1];
    const float* W = (const float*)d_in[2];
    float* out = (float*)d_out;

    decode_sidx_kernel<<<1, 128>>>(idx);
    cudaFuncSetAttribute(mma_gemm_kernel,
                         cudaFuncAttributeMaxDynamicSharedMemorySize, SMEM_BYTES);
    dim3 grid(T_DIM / NT, (C_DIM + MT - 1) / MT, BATCH);   // (4, 5, 128)
    mma_gemm_kernel<<<grid, 256, SMEM_BYTES>>>(x, W, out);
}